// round 3
// baseline (speedup 1.0000x reference)
#include <cuda_runtime.h>

// Problem dims
#define Td 256
#define Bd 512
#define Ed 256
#define Hd 256
#define Cd 256
#define Nd 128
#define Vd 256
#define Od 256
#define EPSf 1e-8f

#define BT   4            // batch rows per CTA
#define NCTA (Bd/BT)      // 128 CTAs
#define NTH  256          // threads per CTA

// 64MB NTM memory state scratch (allowed: __device__ global array)
__device__ float g_mem[(size_t)Bd * Nd * Vd];

struct SM {
    float ci[BT][Ed + Vd];   // 8KB : [x_t | read], reused as [co | r]
    float h [BT][Hd];        // 4KB
    float co[BT][Cd];        // 4KB
    float k [BT][Vd];        // 4KB
    float o [BT][2 * Vd];    // 8KB : [kw | v]
    float rd[BT][Vd];        // 4KB : read / r
    float w [BT][Nd];        // 2KB
    float ww[BT][Nd];        // 2KB
    float kn[BT];
    float kwn[BT];
};

__device__ __forceinline__ float wsum(float v) {
    #pragma unroll
    for (int o = 16; o; o >>= 1) v += __shfl_xor_sync(0xffffffffu, v, o);
    return v;
}
__device__ __forceinline__ float wmax(float v) {
    #pragma unroll
    for (int o = 16; o; o >>= 1) v = fmaxf(v, __shfl_xor_sync(0xffffffffu, v, o));
    return v;
}

// out[BT][NC] = act[BT][KC] @ W[KC][NC] + bias ; thread = (row, 4 cols)
template<int KC, int NC, bool RELU>
__device__ __forceinline__ void gemm4(const float* __restrict__ act,
                                      const float* __restrict__ W,
                                      const float* __restrict__ bias,
                                      float* __restrict__ out)
{
    constexpr int CG = NC / 4;
    for (int task = threadIdx.x; task < BT * CG; task += NTH) {
        int row = task / CG, cg = task - row * CG;
        const float* ar = act + row * KC;
        float4 acc = __ldg((const float4*)bias + cg);
        const float* wp = W + cg * 4;
        #pragma unroll 8
        for (int kk = 0; kk < KC; kk++) {
            float a = ar[kk];
            float4 wv = __ldg((const float4*)(wp + (size_t)kk * NC));
            acc.x = fmaf(a, wv.x, acc.x);
            acc.y = fmaf(a, wv.y, acc.y);
            acc.z = fmaf(a, wv.z, acc.z);
            acc.w = fmaf(a, wv.w, acc.w);
        }
        if (RELU) {
            acc.x = fmaxf(acc.x, 0.f); acc.y = fmaxf(acc.y, 0.f);
            acc.z = fmaxf(acc.z, 0.f); acc.w = fmaxf(acc.w, 0.f);
        }
        *(float4*)(out + row * NC + cg * 4) = acc;
    }
}

// Same, but stores to global with row stride (for the per-step output)
template<int KC, int NC>
__device__ __forceinline__ void gemm4_glob(const float* __restrict__ act,
                                           const float* __restrict__ W,
                                           const float* __restrict__ bias,
                                           float* __restrict__ out,
                                           size_t rstride)
{
    constexpr int CG = NC / 4;
    for (int task = threadIdx.x; task < BT * CG; task += NTH) {
        int row = task / CG, cg = task - row * CG;
        const float* ar = act + row * KC;
        float4 acc = __ldg((const float4*)bias + cg);
        const float* wp = W + cg * 4;
        #pragma unroll 8
        for (int kk = 0; kk < KC; kk++) {
            float a = ar[kk];
            float4 wv = __ldg((const float4*)(wp + (size_t)kk * NC));
            acc.x = fmaf(a, wv.x, acc.x);
            acc.y = fmaf(a, wv.y, acc.y);
            acc.z = fmaf(a, wv.z, acc.z);
            acc.w = fmaf(a, wv.w, acc.w);
        }
        *(float4*)(out + (size_t)row * rstride + cg * 4) = acc;
    }
}

__global__ void __launch_bounds__(NTH, 1) ntm_kernel(
    const float* __restrict__ x,
    const float* __restrict__ W1, const float* __restrict__ b1,
    const float* __restrict__ W2, const float* __restrict__ b2,
    const float* __restrict__ Wr, const float* __restrict__ br,
    const float* __restrict__ Ww, const float* __restrict__ bw,
    const float* __restrict__ Wo, const float* __restrict__ bo,
    const float* __restrict__ init_read,
    const float* __restrict__ mem0,
    float* __restrict__ out)
{
    __shared__ SM s;
    const int tid  = threadIdx.x;
    const int b0   = blockIdx.x * BT;
    const int wid  = tid >> 5, lane = tid & 31;

    // ---- init: mem slice from mem0, read from init_read (re-done every launch) ----
    {
        const float4* src = (const float4*)(mem0 + (size_t)b0 * Nd * Vd);
        float4*       dst = (float4*)(g_mem + (size_t)b0 * Nd * Vd);
        for (int i = tid; i < BT * Nd * Vd / 4; i += NTH) dst[i] = src[i];
        const float4* rs = (const float4*)(init_read + (size_t)b0 * Vd);
        for (int i = tid; i < BT * Vd / 4; i += NTH) ((float4*)s.rd)[i] = rs[i];
    }
    __syncthreads();

    for (int t = 0; t < Td; t++) {
        // ---- ci = [x_t | read] ----
        {
            const float4* xt = (const float4*)(x + ((size_t)t * Bd + b0) * Ed);
            for (int i = tid; i < BT * Ed / 4; i += NTH) {
                int r = i / (Ed / 4), c = i - r * (Ed / 4);
                ((float4*)s.ci[r])[c] = xt[i];   // rows b0..b0+3 contiguous
            }
            for (int i = tid; i < BT * Vd / 4; i += NTH) {
                int r = i / (Vd / 4), c = i - r * (Vd / 4);
                ((float4*)(s.ci[r] + Ed))[c] = ((const float4*)s.rd[r])[c];
            }
        }
        __syncthreads();

        gemm4<Ed + Vd, Hd, true >(&s.ci[0][0], W1, b1, &s.h [0][0]);
        __syncthreads();
        gemm4<Hd,      Cd, false>(&s.h [0][0], W2, b2, &s.co[0][0]);
        __syncthreads();
        gemm4<Cd,      Vd, false>(&s.co[0][0], Wr, br, &s.k [0][0]);
        gemm4<Cd,  2 * Vd, false>(&s.co[0][0], Ww, bw, &s.o [0][0]);
        __syncthreads();

        // ---- key norms: warps 0..3 -> kn, warps 4..7 -> kwn ----
        if (wid < BT) {
            float s2 = 0.f;
            for (int i = lane; i < Vd; i += 32) { float v = s.k[wid][i]; s2 = fmaf(v, v, s2); }
            s2 = wsum(s2);
            if (!lane) s.kn[wid] = fmaxf(sqrtf(s2), EPSf);
        } else {
            int r = wid - BT;
            float s2 = 0.f;
            for (int i = lane; i < Vd; i += 32) { float v = s.o[r][i]; s2 = fmaf(v, v, s2); }
            s2 = wsum(s2);
            if (!lane) s.kwn[r] = fmaxf(sqrtf(s2), EPSf);
        }
        __syncthreads();

        // ---- addressing pass: one mem read computes both dots + mem norms ----
        for (int task = wid; task < BT * Nd; task += NTH / 32) {
            int r = task >> 7, n = task & (Nd - 1);
            const float4* m4 = (const float4*)(g_mem + ((size_t)(b0 + r) * Nd + n) * Vd);
            const float4* k4 = (const float4*)s.k[r];
            const float4* q4 = (const float4*)s.o[r];   // kw = o[:, :V]
            float dk = 0.f, dw = 0.f, nn = 0.f;
            #pragma unroll
            for (int c = lane; c < Vd / 4; c += 32) {
                float4 m = m4[c]; float4 a = k4[c]; float4 b = q4[c];
                dk = fmaf(m.x, a.x, fmaf(m.y, a.y, fmaf(m.z, a.z, fmaf(m.w, a.w, dk))));
                dw = fmaf(m.x, b.x, fmaf(m.y, b.y, fmaf(m.z, b.z, fmaf(m.w, b.w, dw))));
                nn = fmaf(m.x, m.x, fmaf(m.y, m.y, fmaf(m.z, m.z, fmaf(m.w, m.w, nn))));
            }
            dk = wsum(dk); dw = wsum(dw); nn = wsum(nn);
            if (!lane) {
                float mn = fmaxf(sqrtf(nn), EPSf);
                s.w [r][n] = dk / (s.kn [r] * mn);
                s.ww[r][n] = dw / (s.kwn[r] * mn);
            }
        }
        __syncthreads();

        // ---- softmax in-place: warps 0..3 -> w rows, warps 4..7 -> ww rows ----
        {
            float* rowp = (wid < BT) ? s.w[wid] : s.ww[wid - BT];
            float v0 = rowp[lane], v1 = rowp[lane + 32], v2 = rowp[lane + 64], v3 = rowp[lane + 96];
            float mx = wmax(fmaxf(fmaxf(v0, v1), fmaxf(v2, v3)));
            float e0 = __expf(v0 - mx), e1 = __expf(v1 - mx), e2 = __expf(v2 - mx), e3 = __expf(v3 - mx);
            float sm = wsum(e0 + e1 + e2 + e3);
            float inv = 1.f / sm;
            rowp[lane] = e0 * inv; rowp[lane + 32] = e1 * inv;
            rowp[lane + 64] = e2 * inv; rowp[lane + 96] = e3 * inv;
        }
        __syncthreads();

        // ---- fused r readout (old mem) + mem update: thread = (row, 4 v-cols) ----
        {
            int r = tid >> 6, v4 = tid & 63;
            float4* mb = (float4*)(g_mem + (size_t)(b0 + r) * Nd * Vd) + v4;
            float4 vv = ((const float4*)(s.o[r] + Vd))[v4];   // v = o[:, V:]
            float4 ra = make_float4(0.f, 0.f, 0.f, 0.f);
            #pragma unroll 4
            for (int n = 0; n < Nd; n++) {
                float4 m = mb[(size_t)n * (Vd / 4)];
                float wn = s.w[r][n], wwn = s.ww[r][n];
                ra.x = fmaf(wn, m.x, ra.x); ra.y = fmaf(wn, m.y, ra.y);
                ra.z = fmaf(wn, m.z, ra.z); ra.w = fmaf(wn, m.w, ra.w);
                m.x = fmaf(wwn, vv.x, m.x); m.y = fmaf(wwn, vv.y, m.y);
                m.z = fmaf(wwn, vv.z, m.z); m.w = fmaf(wwn, vv.w, m.w);
                mb[(size_t)n * (Vd / 4)] = m;
            }
            ((float4*)s.rd[r])[v4] = ra;
        }
        __syncthreads();

        // ---- [co | r] into ci, then out = ci @ Wo + bo -> global ----
        for (int i = tid; i < BT * Cd / 4; i += NTH) {
            int r = i / (Cd / 4), c = i - r * (Cd / 4);
            ((float4*)s.ci[r])[c]        = ((const float4*)s.co[r])[c];
            ((float4*)(s.ci[r] + Cd))[c] = ((const float4*)s.rd[r])[c];
        }
        __syncthreads();

        gemm4_glob<Cd + Vd, Od>(&s.ci[0][0], Wo, bo,
                                out + ((size_t)t * Bd + b0) * Od, (size_t)Od);
        __syncthreads();
    }
}

extern "C" void kernel_launch(void* const* d_in, const int* in_sizes, int n_in,
                              void* d_out, int out_size)
{
    (void)in_sizes; (void)n_in; (void)out_size;
    const float* x         = (const float*)d_in[0];
    const float* W1        = (const float*)d_in[1];
    const float* b1        = (const float*)d_in[2];
    const float* W2        = (const float*)d_in[3];
    const float* b2        = (const float*)d_in[4];
    const float* Wr        = (const float*)d_in[5];
    const float* br        = (const float*)d_in[6];
    const float* Ww        = (const float*)d_in[7];
    const float* bw        = (const float*)d_in[8];
    const float* Wo        = (const float*)d_in[9];
    const float* bo        = (const float*)d_in[10];
    const float* init_read = (const float*)d_in[11];
    const float* mem0      = (const float*)d_in[12];
    float* out = (float*)d_out;

    ntm_kernel<<<NCTA, NTH>>>(x, W1, b1, W2, b2, Wr, br, Ww, bw, Wo, bo,
                              init_read, mem0, out);
}

// round 4
// speedup vs baseline: 1.4959x; 1.4959x over previous
#include <cuda_runtime.h>

// Problem dims
#define Td 256
#define Bd 512
#define Ed 256
#define Hd 256
#define Cd 256
#define Nd 128
#define Vd 256
#define Od 256
#define EPSf 1e-8f

#define BT   4            // batch rows per CTA
#define NCTA (Bd/BT)      // 128 CTAs
#define NTH  512          // threads per CTA (16 warps)
#define NWARP (NTH/32)

// 64MB NTM memory state scratch (allowed: __device__ global array)
__device__ float g_mem[(size_t)Bd * Nd * Vd];

struct SM {
    float ci[BT][Ed + Vd];       // 8KB : [x_t | read], reused as [co | r]
    float h [BT][Hd];            // 4KB
    float co[BT][Cd];            // 4KB
    float k [BT][Vd];            // 4KB
    float o [BT][2 * Vd];        // 8KB : [kw | v]
    float rd[BT][Vd];            // 4KB : read / r
    float w [BT][Nd];            // 2KB
    float ww[BT][Nd];            // 2KB
    float scratch[2][BT * 256];  // 8KB : K-split GEMM partials / readout partials
    float kn[BT];
    float kwn[BT];
};

__device__ __forceinline__ float wsum(float v) {
    #pragma unroll
    for (int o = 16; o; o >>= 1) v += __shfl_xor_sync(0xffffffffu, v, o);
    return v;
}
__device__ __forceinline__ float wmax(float v) {
    #pragma unroll
    for (int o = 16; o; o >>= 1) v = fmaxf(v, __shfl_xor_sync(0xffffffffu, v, o));
    return v;
}

// K-split GEMM: out[BT][NC] = act[BT][KC] @ W[KC][NC] + bias.
// 512 threads = 2 K-halves x 256 (row,col4) tasks. Partials land in smem
// scratch; the first 256 threads combine. Caller must __syncthreads() after.
template<int KC, int NC, bool RELU, bool GLOB>
__device__ __forceinline__ void gemm_split(const float* __restrict__ act,
                                           const float* __restrict__ W,
                                           const float* __restrict__ bias,
                                           float* __restrict__ dst,
                                           size_t rstride,
                                           float* __restrict__ scratch)
{
    constexpr int CG    = NC / 4;     // 64
    constexpr int TASKS = BT * CG;    // 256
    static_assert(2 * TASKS == NTH, "split gemm needs NTH = 2*TASKS");

    const int tid  = threadIdx.x;
    const int half = tid >> 8;                 // 0 or 1
    const int task = tid & (TASKS - 1);
    const int row  = task / CG, cg = task - row * CG;

    const float* ar = act + row * KC + half * (KC / 2);
    const float* wp = W + (size_t)half * (KC / 2) * NC + cg * 4;

    float4 acc;
    if (half == 0) acc = __ldg((const float4*)bias + cg);
    else           acc = make_float4(0.f, 0.f, 0.f, 0.f);

    #pragma unroll 8
    for (int kk = 0; kk < KC / 2; kk++) {
        float a = ar[kk];
        float4 wv = __ldg((const float4*)(wp + (size_t)kk * NC));
        acc.x = fmaf(a, wv.x, acc.x);
        acc.y = fmaf(a, wv.y, acc.y);
        acc.z = fmaf(a, wv.z, acc.z);
        acc.w = fmaf(a, wv.w, acc.w);
    }
    ((float4*)scratch)[half * TASKS + task] = acc;
    __syncthreads();

    if (tid < TASKS) {
        float4 p0 = ((const float4*)scratch)[task];
        float4 p1 = ((const float4*)scratch)[TASKS + task];
        float4 v = make_float4(p0.x + p1.x, p0.y + p1.y, p0.z + p1.z, p0.w + p1.w);
        if (RELU) {
            v.x = fmaxf(v.x, 0.f); v.y = fmaxf(v.y, 0.f);
            v.z = fmaxf(v.z, 0.f); v.w = fmaxf(v.w, 0.f);
        }
        if (GLOB) *(float4*)(dst + (size_t)row * rstride + cg * 4) = v;
        else      *(float4*)(dst + row * NC + cg * 4) = v;
    }
}

// Full-K GEMM (for NC=512 where tasks already = NTH)
template<int KC, int NC>
__device__ __forceinline__ void gemm_full(const float* __restrict__ act,
                                          const float* __restrict__ W,
                                          const float* __restrict__ bias,
                                          float* __restrict__ out)
{
    constexpr int CG = NC / 4;                  // 128
    static_assert(BT * CG == NTH, "full gemm needs NTH = BT*CG");
    const int task = threadIdx.x;
    const int row = task / CG, cg = task - row * CG;
    const float* ar = act + row * KC;
    float4 acc = __ldg((const float4*)bias + cg);
    const float* wp = W + cg * 4;
    #pragma unroll 8
    for (int kk = 0; kk < KC; kk++) {
        float a = ar[kk];
        float4 wv = __ldg((const float4*)(wp + (size_t)kk * NC));
        acc.x = fmaf(a, wv.x, acc.x);
        acc.y = fmaf(a, wv.y, acc.y);
        acc.z = fmaf(a, wv.z, acc.z);
        acc.w = fmaf(a, wv.w, acc.w);
    }
    *(float4*)(out + row * NC + cg * 4) = acc;
}

__global__ void __launch_bounds__(NTH, 1) ntm_kernel(
    const float* __restrict__ x,
    const float* __restrict__ W1, const float* __restrict__ b1,
    const float* __restrict__ W2, const float* __restrict__ b2,
    const float* __restrict__ Wr, const float* __restrict__ br,
    const float* __restrict__ Ww, const float* __restrict__ bw,
    const float* __restrict__ Wo, const float* __restrict__ bo,
    const float* __restrict__ init_read,
    const float* __restrict__ mem0,
    float* __restrict__ out)
{
    __shared__ SM s;
    const int tid  = threadIdx.x;
    const int b0   = blockIdx.x * BT;
    const int wid  = tid >> 5, lane = tid & 31;

    // ---- init: mem slice from mem0, read from init_read ----
    {
        const float4* src = (const float4*)(mem0 + (size_t)b0 * Nd * Vd);
        float4*       dst = (float4*)(g_mem + (size_t)b0 * Nd * Vd);
        for (int i = tid; i < BT * Nd * Vd / 4; i += NTH) dst[i] = src[i];
        const float4* rs = (const float4*)(init_read + (size_t)b0 * Vd);
        for (int i = tid; i < BT * Vd / 4; i += NTH) ((float4*)s.rd)[i] = rs[i];
    }
    __syncthreads();

    for (int t = 0; t < Td; t++) {
        // ---- ci = [x_t | read] ----
        {
            const float4* xt = (const float4*)(x + ((size_t)t * Bd + b0) * Ed);
            for (int i = tid; i < BT * Ed / 4; i += NTH) {
                int r = i / (Ed / 4), c = i - r * (Ed / 4);
                ((float4*)s.ci[r])[c] = xt[i];
            }
            for (int i = tid; i < BT * Vd / 4; i += NTH) {
                int r = i / (Vd / 4), c = i - r * (Vd / 4);
                ((float4*)(s.ci[r] + Ed))[c] = ((const float4*)s.rd[r])[c];
            }
        }
        __syncthreads();

        gemm_split<Ed + Vd, Hd, true , false>(&s.ci[0][0], W1, b1, &s.h [0][0], 0, &s.scratch[0][0]);
        __syncthreads();
        gemm_split<Hd,      Cd, false, false>(&s.h [0][0], W2, b2, &s.co[0][0], 0, &s.scratch[0][0]);
        __syncthreads();
        // o = co @ Ww + bw (512 cols: one task per thread, full K)
        gemm_full<Cd, 2 * Vd>(&s.co[0][0], Ww, bw, &s.o[0][0]);
        // k = co @ Wr + br (K-split; internal sync also covers gemm_full's writes)
        gemm_split<Cd,      Vd, false, false>(&s.co[0][0], Wr, br, &s.k [0][0], 0, &s.scratch[0][0]);
        __syncthreads();

        // ---- key norms: warps 0..3 -> kn, warps 4..7 -> kwn ----
        if (wid < BT) {
            float s2 = 0.f;
            for (int i = lane; i < Vd; i += 32) { float v = s.k[wid][i]; s2 = fmaf(v, v, s2); }
            s2 = wsum(s2);
            if (!lane) s.kn[wid] = fmaxf(sqrtf(s2), EPSf);
        } else if (wid < 2 * BT) {
            int r = wid - BT;
            float s2 = 0.f;
            for (int i = lane; i < Vd; i += 32) { float v = s.o[r][i]; s2 = fmaf(v, v, s2); }
            s2 = wsum(s2);
            if (!lane) s.kwn[r] = fmaxf(sqrtf(s2), EPSf);
        }
        __syncthreads();

        // ---- addressing pass: one mem read -> both dots + mem norms (16 warps) ----
        for (int task = wid; task < BT * Nd; task += NWARP) {
            int r = task >> 7, n = task & (Nd - 1);
            const float4* m4 = (const float4*)(g_mem + ((size_t)(b0 + r) * Nd + n) * Vd);
            const float4* k4 = (const float4*)s.k[r];
            const float4* q4 = (const float4*)s.o[r];   // kw = o[:, :V]
            float dk = 0.f, dw = 0.f, nn = 0.f;
            #pragma unroll
            for (int c = lane; c < Vd / 4; c += 32) {
                float4 m = m4[c]; float4 a = k4[c]; float4 b = q4[c];
                dk = fmaf(m.x, a.x, fmaf(m.y, a.y, fmaf(m.z, a.z, fmaf(m.w, a.w, dk))));
                dw = fmaf(m.x, b.x, fmaf(m.y, b.y, fmaf(m.z, b.z, fmaf(m.w, b.w, dw))));
                nn = fmaf(m.x, m.x, fmaf(m.y, m.y, fmaf(m.z, m.z, fmaf(m.w, m.w, nn))));
            }
            dk = wsum(dk); dw = wsum(dw); nn = wsum(nn);
            if (!lane) {
                float mn = fmaxf(sqrtf(nn), EPSf);
                s.w [r][n] = dk / (s.kn [r] * mn);
                s.ww[r][n] = dw / (s.kwn[r] * mn);
            }
        }
        __syncthreads();

        // ---- softmax in-place: warps 0..3 -> w rows, 4..7 -> ww rows ----
        if (wid < 2 * BT) {
            float* rowp = (wid < BT) ? s.w[wid] : s.ww[wid - BT];
            float v0 = rowp[lane], v1 = rowp[lane + 32], v2 = rowp[lane + 64], v3 = rowp[lane + 96];
            float mx = wmax(fmaxf(fmaxf(v0, v1), fmaxf(v2, v3)));
            float e0 = __expf(v0 - mx), e1 = __expf(v1 - mx), e2 = __expf(v2 - mx), e3 = __expf(v3 - mx);
            float sm = wsum(e0 + e1 + e2 + e3);
            float inv = 1.f / sm;
            rowp[lane] = e0 * inv; rowp[lane + 32] = e1 * inv;
            rowp[lane + 64] = e2 * inv; rowp[lane + 96] = e3 * inv;
        }
        __syncthreads();

        // ---- fused r readout (old mem) + mem update, split over 2 n-halves ----
        {
            int nh = tid >> 8;              // n-half: 0 or 1
            int r  = (tid >> 6) & 3;        // batch row
            int v4 = tid & 63;              // float4 column
            float4* mb = (float4*)(g_mem + (size_t)(b0 + r) * Nd * Vd) + v4;
            float4 vv = ((const float4*)(s.o[r] + Vd))[v4];   // v = o[:, V:]
            float4 ra = make_float4(0.f, 0.f, 0.f, 0.f);
            const int n0 = nh * (Nd / 2);
            #pragma unroll 4
            for (int j = 0; j < Nd / 2; j++) {
                int n = n0 + j;
                float4 m = mb[(size_t)n * (Vd / 4)];
                float wn = s.w[r][n], wwn = s.ww[r][n];
                ra.x = fmaf(wn, m.x, ra.x); ra.y = fmaf(wn, m.y, ra.y);
                ra.z = fmaf(wn, m.z, ra.z); ra.w = fmaf(wn, m.w, ra.w);
                m.x = fmaf(wwn, vv.x, m.x); m.y = fmaf(wwn, vv.y, m.y);
                m.z = fmaf(wwn, vv.z, m.z); m.w = fmaf(wwn, vv.w, m.w);
                mb[(size_t)n * (Vd / 4)] = m;
            }
            ((float4*)(s.scratch[nh]))[r * 64 + v4] = ra;
        }
        __syncthreads();

        // combine readout halves -> rd, and build [co | r] into ci
        if (tid < BT * Vd / 4) {
            float4 p0 = ((const float4*)(s.scratch[0]))[tid];
            float4 p1 = ((const float4*)(s.scratch[1]))[tid];
            int r = tid >> 6, c = tid & 63;
            float4 rv = make_float4(p0.x + p1.x, p0.y + p1.y, p0.z + p1.z, p0.w + p1.w);
            ((float4*)s.rd[r])[c] = rv;
            ((float4*)(s.ci[r] + Cd))[c] = rv;
            ((float4*)s.ci[r])[c] = ((const float4*)s.co[r])[c];
        }
        __syncthreads();

        gemm_split<Cd + Vd, Od, false, true>(&s.ci[0][0], Wo, bo,
                                             out + ((size_t)t * Bd + b0) * Od,
                                             (size_t)Od, &s.scratch[0][0]);
        __syncthreads();
    }
}

extern "C" void kernel_launch(void* const* d_in, const int* in_sizes, int n_in,
                              void* d_out, int out_size)
{
    (void)in_sizes; (void)n_in; (void)out_size;
    const float* x         = (const float*)d_in[0];
    const float* W1        = (const float*)d_in[1];
    const float* b1        = (const float*)d_in[2];
    const float* W2        = (const float*)d_in[3];
    const float* b2        = (const float*)d_in[4];
    const float* Wr        = (const float*)d_in[5];
    const float* br        = (const float*)d_in[6];
    const float* Ww        = (const float*)d_in[7];
    const float* bw        = (const float*)d_in[8];
    const float* Wo        = (const float*)d_in[9];
    const float* bo        = (const float*)d_in[10];
    const float* init_read = (const float*)d_in[11];
    const float* mem0      = (const float*)d_in[12];
    float* out = (float*)d_out;

    ntm_kernel<<<NCTA, NTH>>>(x, W1, b1, W2, b2, Wr, br, Ww, bw, Wo, bo,
                              init_read, mem0, out);
}

// round 5
// speedup vs baseline: 2.1590x; 1.4433x over previous
#include <cuda_runtime.h>

// Problem dims
#define Td 256
#define Bd 512
#define Ed 256
#define Hd 256
#define Cd 256
#define Nd 128
#define Vd 256
#define Od 256
#define EPSf 1e-8f

#define BT   4            // batch rows per CTA
#define NCTA (Bd/BT)      // 128 CTAs
#define NTH  512          // threads per CTA (16 warps)
#define NWARP (NTH/32)

// 64MB NTM memory state scratch (allowed: __device__ global array)
__device__ float g_mem[(size_t)Bd * Nd * Vd];

// Dynamic smem layout (float4 arrays first for alignment). ~69.7KB total.
struct SM {
    float4 scratch[8 * BT * 64];   // 32KB: K-slice GEMM partials / readout partials
    float4 ciT[Ed + Vd];           // 8KB : transposed [x_t | read], ciT[k] = rows 0..3
    float4 hT [Hd];                // 4KB : transposed hidden
    float4 woT[Cd + Vd];           // 8KB : transposed [co | r]  (Wo input; first half = co = Wr/Ww input)
    float  k [BT][Vd];             // 4KB : read key (row-major, for norms/addressing)
    float  o [BT][2 * Vd];         // 8KB : [kw | v] (row-major)
    float  w [BT][Nd];             // 2KB
    float  ww[BT][Nd];             // 2KB
    float  kn[BT];
    float  kwn[BT];
};

__device__ __forceinline__ float wsum(float v) {
    #pragma unroll
    for (int o = 16; o; o >>= 1) v += __shfl_xor_sync(0xffffffffu, v, o);
    return v;
}
__device__ __forceinline__ float wmax(float v) {
    #pragma unroll
    for (int o = 16; o; o >>= 1) v = fmaxf(v, __shfl_xor_sync(0xffffffffu, v, o));
    return v;
}

// Register-tiled K-sliced GEMM main pass.
// actT[k] = float4 of the 4 batch rows' activation at k.
// Thread (ks, cg) loads each weight float4 ONCE, applies to 4 rows (16 FMA / LDG.128).
// Partials -> scratch[(ks*BT+row)*CG + cg]. Ends with __syncthreads().
template<int KC, int NC>
__device__ __forceinline__ void gemm_main(const float4* __restrict__ actT,
                                          const float* __restrict__ W,
                                          const float* __restrict__ bias,
                                          float4* __restrict__ scratch)
{
    constexpr int CG = NC / 4;          // col groups (64 or 128)
    constexpr int KS = NTH / CG;        // K slices (8 or 4)
    constexpr int KL = KC / KS;         // k per slice
    const int tid = threadIdx.x;
    const int ks = tid / CG;
    const int cg = tid - ks * CG;

    const float4* wp = (const float4*)(W + (size_t)(ks * KL) * NC) + cg;
    const float4* ap = actT + ks * KL;

    float4 a0, a1, a2, a3;
    if (ks == 0) { float4 b = __ldg((const float4*)bias + cg); a0 = a1 = a2 = a3 = b; }
    else { a0 = a1 = a2 = a3 = make_float4(0.f, 0.f, 0.f, 0.f); }

    #pragma unroll 8
    for (int kk = 0; kk < KL; kk++) {
        float4 av = ap[kk];                              // broadcast LDS.128 (4 rows)
        float4 wv = __ldg(wp + (size_t)kk * (NC / 4));   // weight LDG.128, loaded once
        a0.x = fmaf(av.x, wv.x, a0.x); a0.y = fmaf(av.x, wv.y, a0.y);
        a0.z = fmaf(av.x, wv.z, a0.z); a0.w = fmaf(av.x, wv.w, a0.w);
        a1.x = fmaf(av.y, wv.x, a1.x); a1.y = fmaf(av.y, wv.y, a1.y);
        a1.z = fmaf(av.y, wv.z, a1.z); a1.w = fmaf(av.y, wv.w, a1.w);
        a2.x = fmaf(av.z, wv.x, a2.x); a2.y = fmaf(av.z, wv.y, a2.y);
        a2.z = fmaf(av.z, wv.z, a2.z); a2.w = fmaf(av.z, wv.w, a2.w);
        a3.x = fmaf(av.w, wv.x, a3.x); a3.y = fmaf(av.w, wv.y, a3.y);
        a3.z = fmaf(av.w, wv.z, a3.z); a3.w = fmaf(av.w, wv.w, a3.w);
    }
    scratch[(ks * BT + 0) * CG + cg] = a0;
    scratch[(ks * BT + 1) * CG + cg] = a1;
    scratch[(ks * BT + 2) * CG + cg] = a2;
    scratch[(ks * BT + 3) * CG + cg] = a3;
    __syncthreads();
}

// Combine K-slice partials. MODE 0: row-major smem. MODE 1: transposed smem.
// MODE 2: row-major global. Caller must __syncthreads() after.
template<int NC, int KS, bool RELU, int MODE>
__device__ __forceinline__ void gemm_combine(const float4* __restrict__ scratch,
                                             float* __restrict__ dst,
                                             float4* __restrict__ dstT,
                                             size_t rstride)
{
    constexpr int CG = NC / 4;
    constexpr int TASKS = BT * CG;      // 256 or 512
    const int tid = threadIdx.x;
    if (TASKS == NTH || tid < TASKS) {
        const int row = tid / CG, cg = tid - row * CG;
        float4 v = scratch[row * CG + cg];
        #pragma unroll
        for (int ks = 1; ks < KS; ks++) {
            float4 p = scratch[(ks * BT + row) * CG + cg];
            v.x += p.x; v.y += p.y; v.z += p.z; v.w += p.w;
        }
        if (RELU) {
            v.x = fmaxf(v.x, 0.f); v.y = fmaxf(v.y, 0.f);
            v.z = fmaxf(v.z, 0.f); v.w = fmaxf(v.w, 0.f);
        }
        if (MODE == 0) {
            *(float4*)(dst + row * NC + cg * 4) = v;
        } else if (MODE == 1) {
            ((float*)(dstT + cg * 4 + 0))[row] = v.x;
            ((float*)(dstT + cg * 4 + 1))[row] = v.y;
            ((float*)(dstT + cg * 4 + 2))[row] = v.z;
            ((float*)(dstT + cg * 4 + 3))[row] = v.w;
        } else {
            *(float4*)(dst + (size_t)row * rstride + cg * 4) = v;
        }
    }
}

__global__ void __launch_bounds__(NTH, 1) ntm_kernel(
    const float* __restrict__ x,
    const float* __restrict__ W1, const float* __restrict__ b1,
    const float* __restrict__ W2, const float* __restrict__ b2,
    const float* __restrict__ Wr, const float* __restrict__ br,
    const float* __restrict__ Ww, const float* __restrict__ bw,
    const float* __restrict__ Wo, const float* __restrict__ bo,
    const float* __restrict__ init_read,
    const float* __restrict__ mem0,
    float* __restrict__ out)
{
    extern __shared__ char smraw[];
    SM& s = *reinterpret_cast<SM*>(smraw);

    const int tid  = threadIdx.x;
    const int b0   = blockIdx.x * BT;
    const int wid  = tid >> 5, lane = tid & 31;

    // ---- init: mem slice from mem0, transposed read from init_read ----
    {
        const float4* src = (const float4*)(mem0 + (size_t)b0 * Nd * Vd);
        float4*       dst = (float4*)(g_mem + (size_t)b0 * Nd * Vd);
        for (int i = tid; i < BT * Nd * Vd / 4; i += NTH) dst[i] = src[i];
        if (tid < BT * Vd / 4) {
            int r = tid >> 6, c4 = tid & 63;
            float4 v = __ldg((const float4*)(init_read + (size_t)(b0 + r) * Vd) + c4);
            ((float*)(s.ciT + Ed + c4 * 4 + 0))[r] = v.x;
            ((float*)(s.ciT + Ed + c4 * 4 + 1))[r] = v.y;
            ((float*)(s.ciT + Ed + c4 * 4 + 2))[r] = v.z;
            ((float*)(s.ciT + Ed + c4 * 4 + 3))[r] = v.w;
        }
    }
    __syncthreads();

    for (int t = 0; t < Td; t++) {
        // ---- stage x_t transposed into ciT[0..Ed) ----
        if (tid < BT * Ed / 4) {
            int r = tid >> 6, c4 = tid & 63;
            float4 v = __ldg((const float4*)(x + ((size_t)t * Bd + b0 + r) * Ed) + c4);
            ((float*)(s.ciT + c4 * 4 + 0))[r] = v.x;
            ((float*)(s.ciT + c4 * 4 + 1))[r] = v.y;
            ((float*)(s.ciT + c4 * 4 + 2))[r] = v.z;
            ((float*)(s.ciT + c4 * 4 + 3))[r] = v.w;
        }
        __syncthreads();

        // h = relu(ci @ W1 + b1) -> hT
        gemm_main<Ed + Vd, Hd>(s.ciT, W1, b1, s.scratch);
        gemm_combine<Hd, NTH / (Hd / 4), true, 1>(s.scratch, nullptr, s.hT, 0);
        __syncthreads();

        // co = h @ W2 + b2 -> woT[0..Cd)
        gemm_main<Hd, Cd>(s.hT, W2, b2, s.scratch);
        gemm_combine<Cd, NTH / (Cd / 4), false, 1>(s.scratch, nullptr, s.woT, 0);
        __syncthreads();

        // k = co @ Wr + br -> row-major s.k
        gemm_main<Cd, Vd>(s.woT, Wr, br, s.scratch);
        gemm_combine<Vd, NTH / (Vd / 4), false, 0>(s.scratch, &s.k[0][0], nullptr, 0);
        __syncthreads();

        // o = co @ Ww + bw -> row-major s.o
        gemm_main<Cd, 2 * Vd>(s.woT, Ww, bw, s.scratch);
        gemm_combine<2 * Vd, NTH / (2 * Vd / 4), false, 0>(s.scratch, &s.o[0][0], nullptr, 0);
        __syncthreads();

        // ---- key norms: warps 0..3 -> kn, warps 4..7 -> kwn ----
        if (wid < BT) {
            float s2 = 0.f;
            for (int i = lane; i < Vd; i += 32) { float v = s.k[wid][i]; s2 = fmaf(v, v, s2); }
            s2 = wsum(s2);
            if (!lane) s.kn[wid] = fmaxf(sqrtf(s2), EPSf);
        } else if (wid < 2 * BT) {
            int r = wid - BT;
            float s2 = 0.f;
            for (int i = lane; i < Vd; i += 32) { float v = s.o[r][i]; s2 = fmaf(v, v, s2); }
            s2 = wsum(s2);
            if (!lane) s.kwn[r] = fmaxf(sqrtf(s2), EPSf);
        }
        __syncthreads();

        // ---- addressing pass: one mem read -> both dots + mem norms ----
        for (int task = wid; task < BT * Nd; task += NWARP) {
            int r = task >> 7, n = task & (Nd - 1);
            const float4* m4 = (const float4*)(g_mem + ((size_t)(b0 + r) * Nd + n) * Vd);
            const float4* k4 = (const float4*)s.k[r];
            const float4* q4 = (const float4*)s.o[r];   // kw = o[:, :V]
            float dk = 0.f, dw = 0.f, nn = 0.f;
            #pragma unroll
            for (int c = lane; c < Vd / 4; c += 32) {
                float4 m = m4[c]; float4 a = k4[c]; float4 b = q4[c];
                dk = fmaf(m.x, a.x, fmaf(m.y, a.y, fmaf(m.z, a.z, fmaf(m.w, a.w, dk))));
                dw = fmaf(m.x, b.x, fmaf(m.y, b.y, fmaf(m.z, b.z, fmaf(m.w, b.w, dw))));
                nn = fmaf(m.x, m.x, fmaf(m.y, m.y, fmaf(m.z, m.z, fmaf(m.w, m.w, nn))));
            }
            dk = wsum(dk); dw = wsum(dw); nn = wsum(nn);
            if (!lane) {
                float mn = fmaxf(sqrtf(nn), EPSf);
                s.w [r][n] = dk / (s.kn [r] * mn);
                s.ww[r][n] = dw / (s.kwn[r] * mn);
            }
        }
        __syncthreads();

        // ---- softmax in-place: warps 0..3 -> w rows, 4..7 -> ww rows ----
        if (wid < 2 * BT) {
            float* rowp = (wid < BT) ? s.w[wid] : s.ww[wid - BT];
            float v0 = rowp[lane], v1 = rowp[lane + 32], v2 = rowp[lane + 64], v3 = rowp[lane + 96];
            float mx = wmax(fmaxf(fmaxf(v0, v1), fmaxf(v2, v3)));
            float e0 = __expf(v0 - mx), e1 = __expf(v1 - mx), e2 = __expf(v2 - mx), e3 = __expf(v3 - mx);
            float sm = wsum(e0 + e1 + e2 + e3);
            float inv = 1.f / sm;
            rowp[lane] = e0 * inv; rowp[lane + 32] = e1 * inv;
            rowp[lane + 64] = e2 * inv; rowp[lane + 96] = e3 * inv;
        }
        __syncthreads();

        // ---- fused r readout (old mem) + mem update, split over 2 n-halves ----
        {
            int nh = tid >> 8;              // n-half: 0 or 1
            int r  = (tid >> 6) & 3;        // batch row
            int v4 = tid & 63;              // float4 column
            float4* mb = (float4*)(g_mem + (size_t)(b0 + r) * Nd * Vd) + v4;
            float4 vv = ((const float4*)(s.o[r] + Vd))[v4];   // v = o[:, V:]
            float4 ra = make_float4(0.f, 0.f, 0.f, 0.f);
            const int n0 = nh * (Nd / 2);
            #pragma unroll 4
            for (int j = 0; j < Nd / 2; j++) {
                int n = n0 + j;
                float4 m = mb[(size_t)n * (Vd / 4)];
                float wn = s.w[r][n], wwn = s.ww[r][n];
                ra.x = fmaf(wn, m.x, ra.x); ra.y = fmaf(wn, m.y, ra.y);
                ra.z = fmaf(wn, m.z, ra.z); ra.w = fmaf(wn, m.w, ra.w);
                m.x = fmaf(wwn, vv.x, m.x); m.y = fmaf(wwn, vv.y, m.y);
                m.z = fmaf(wwn, vv.z, m.z); m.w = fmaf(wwn, vv.w, m.w);
                mb[(size_t)n * (Vd / 4)] = m;
            }
            s.scratch[(nh * BT + r) * 64 + v4] = ra;
        }
        __syncthreads();

        // combine readout halves -> transposed r into woT[Cd..] and ciT[Ed..]
        if (tid < BT * Vd / 4) {
            int r = tid >> 6, c4 = tid & 63;
            float4 p0 = s.scratch[r * 64 + c4];
            float4 p1 = s.scratch[(BT + r) * 64 + c4];
            float4 rv = make_float4(p0.x + p1.x, p0.y + p1.y, p0.z + p1.z, p0.w + p1.w);
            ((float*)(s.woT + Cd + c4 * 4 + 0))[r] = rv.x;
            ((float*)(s.woT + Cd + c4 * 4 + 1))[r] = rv.y;
            ((float*)(s.woT + Cd + c4 * 4 + 2))[r] = rv.z;
            ((float*)(s.woT + Cd + c4 * 4 + 3))[r] = rv.w;
            ((float*)(s.ciT + Ed + c4 * 4 + 0))[r] = rv.x;
            ((float*)(s.ciT + Ed + c4 * 4 + 1))[r] = rv.y;
            ((float*)(s.ciT + Ed + c4 * 4 + 2))[r] = rv.z;
            ((float*)(s.ciT + Ed + c4 * 4 + 3))[r] = rv.w;
        }
        __syncthreads();

        // out = [co | r] @ Wo + bo -> global
        gemm_main<Cd + Vd, Od>(s.woT, Wo, bo, s.scratch);
        gemm_combine<Od, NTH / (Od / 4), false, 2>(s.scratch,
                                                   out + ((size_t)t * Bd + b0) * Od,
                                                   nullptr, (size_t)Od);
        __syncthreads();
    }
}

extern "C" void kernel_launch(void* const* d_in, const int* in_sizes, int n_in,
                              void* d_out, int out_size)
{
    (void)in_sizes; (void)n_in; (void)out_size;
    const float* x         = (const float*)d_in[0];
    const float* W1        = (const float*)d_in[1];
    const float* b1        = (const float*)d_in[2];
    const float* W2        = (const float*)d_in[3];
    const float* b2        = (const float*)d_in[4];
    const float* Wr        = (const float*)d_in[5];
    const float* br        = (const float*)d_in[6];
    const float* Ww        = (const float*)d_in[7];
    const float* bw        = (const float*)d_in[8];
    const float* Wo        = (const float*)d_in[9];
    const float* bo        = (const float*)d_in[10];
    const float* init_read = (const float*)d_in[11];
    const float* mem0      = (const float*)d_in[12];
    float* out = (float*)d_out;

    int smem = (int)sizeof(SM);
    cudaFuncSetAttribute(ntm_kernel, cudaFuncAttributeMaxDynamicSharedMemorySize, smem);
    ntm_kernel<<<NCTA, NTH, smem>>>(x, W1, b1, W2, b2, Wr, br, Ww, bw, Wo, bo,
                                    init_read, mem0, out);
}

// round 6
// speedup vs baseline: 2.1794x; 1.0094x over previous
#include <cuda_runtime.h>

// Problem dims
#define Td 256
#define Bd 512
#define Ed 256
#define Hd 256
#define Cd 256
#define Nd 128
#define Vd 256
#define Od 256
#define EPSf 1e-8f

#define BT   4            // batch rows per CTA
#define NCTA (Bd/BT)      // 128 CTAs
#define NTH  1024         // threads per CTA (32 warps)
#define NWARP (NTH/32)

// 64MB NTM memory state scratch (allowed: __device__ global array)
__device__ float g_mem[(size_t)Bd * Nd * Vd];

// Dynamic smem layout (float4 arrays first for alignment). ~100KB total.
struct SM {
    float4 scratch[16 * BT * 64];  // 64KB: K-slice GEMM partials / readout partials
    float4 ciT[Ed + Vd];           // 8KB : transposed [x_t | read], ciT[k] = rows 0..3
    float4 hT [Hd];                // 4KB : transposed hidden
    float4 woT[Cd + Vd];           // 8KB : transposed [co | r]
    float  k [BT][Vd];             // 4KB : read key (row-major)
    float  o [BT][2 * Vd];         // 8KB : [kw | v] (row-major)
    float  w [BT][Nd];             // 2KB
    float  ww[BT][Nd];             // 2KB
    float  kn[BT];
    float  kwn[BT];
};

__device__ __forceinline__ float wsum(float v) {
    #pragma unroll
    for (int o = 16; o; o >>= 1) v += __shfl_xor_sync(0xffffffffu, v, o);
    return v;
}
__device__ __forceinline__ float wmax(float v) {
    #pragma unroll
    for (int o = 16; o; o >>= 1) v = fmaxf(v, __shfl_xor_sync(0xffffffffu, v, o));
    return v;
}

// Register-tiled K-sliced GEMM main pass.
// actT[k] = float4 of the 4 batch rows' activation at k.
// Thread (ks, cg): each weight float4 loaded ONCE, applied to 4 rows (16 FMA/LDG.128).
// Partials -> scratch[(ks*BT+row)*CG + cg]. Ends with __syncthreads().
template<int KC, int NC>
__device__ __forceinline__ void gemm_main(const float4* __restrict__ actT,
                                          const float* __restrict__ W,
                                          const float* __restrict__ bias,
                                          float4* __restrict__ scratch)
{
    constexpr int CG = NC / 4;          // col groups (64 or 128)
    constexpr int KS = NTH / CG;        // K slices (16 or 8)
    constexpr int KL = KC / KS;         // k per slice
    const int tid = threadIdx.x;
    const int ks = tid / CG;
    const int cg = tid - ks * CG;

    const float4* wp = (const float4*)(W + (size_t)(ks * KL) * NC) + cg;
    const float4* ap = actT + ks * KL;

    float4 a0, a1, a2, a3;
    if (ks == 0) { float4 b = __ldg((const float4*)bias + cg); a0 = a1 = a2 = a3 = b; }
    else { a0 = a1 = a2 = a3 = make_float4(0.f, 0.f, 0.f, 0.f); }

    #pragma unroll 4
    for (int kk = 0; kk < KL; kk++) {
        float4 av = ap[kk];                              // broadcast LDS.128 (4 rows)
        float4 wv = __ldg(wp + (size_t)kk * (NC / 4));   // weight LDG.128, loaded once
        a0.x = fmaf(av.x, wv.x, a0.x); a0.y = fmaf(av.x, wv.y, a0.y);
        a0.z = fmaf(av.x, wv.z, a0.z); a0.w = fmaf(av.x, wv.w, a0.w);
        a1.x = fmaf(av.y, wv.x, a1.x); a1.y = fmaf(av.y, wv.y, a1.y);
        a1.z = fmaf(av.y, wv.z, a1.z); a1.w = fmaf(av.y, wv.w, a1.w);
        a2.x = fmaf(av.z, wv.x, a2.x); a2.y = fmaf(av.z, wv.y, a2.y);
        a2.z = fmaf(av.z, wv.z, a2.z); a2.w = fmaf(av.z, wv.w, a2.w);
        a3.x = fmaf(av.w, wv.x, a3.x); a3.y = fmaf(av.w, wv.y, a3.y);
        a3.z = fmaf(av.w, wv.z, a3.z); a3.w = fmaf(av.w, wv.w, a3.w);
    }
    scratch[(ks * BT + 0) * CG + cg] = a0;
    scratch[(ks * BT + 1) * CG + cg] = a1;
    scratch[(ks * BT + 2) * CG + cg] = a2;
    scratch[(ks * BT + 3) * CG + cg] = a3;
    __syncthreads();
}

// Combine K-slice partials. MODE 0: row-major smem. MODE 1: transposed smem.
// MODE 2: row-major global. Caller must __syncthreads() after.
template<int NC, int KS, bool RELU, int MODE>
__device__ __forceinline__ void gemm_combine(const float4* __restrict__ scratch,
                                             float* __restrict__ dst,
                                             float4* __restrict__ dstT,
                                             size_t rstride)
{
    constexpr int CG = NC / 4;
    constexpr int TASKS = BT * CG;      // 256 or 512
    const int tid = threadIdx.x;
    if (tid < TASKS) {
        const int row = tid / CG, cg = tid - row * CG;
        float4 v = scratch[row * CG + cg];
        #pragma unroll
        for (int ks = 1; ks < KS; ks++) {
            float4 p = scratch[(ks * BT + row) * CG + cg];
            v.x += p.x; v.y += p.y; v.z += p.z; v.w += p.w;
        }
        if (RELU) {
            v.x = fmaxf(v.x, 0.f); v.y = fmaxf(v.y, 0.f);
            v.z = fmaxf(v.z, 0.f); v.w = fmaxf(v.w, 0.f);
        }
        if (MODE == 0) {
            *(float4*)(dst + row * NC + cg * 4) = v;
        } else if (MODE == 1) {
            ((float*)(dstT + cg * 4 + 0))[row] = v.x;
            ((float*)(dstT + cg * 4 + 1))[row] = v.y;
            ((float*)(dstT + cg * 4 + 2))[row] = v.z;
            ((float*)(dstT + cg * 4 + 3))[row] = v.w;
        } else {
            *(float4*)(dst + (size_t)row * rstride + cg * 4) = v;
        }
    }
}

__global__ void __launch_bounds__(NTH, 1) ntm_kernel(
    const float* __restrict__ x,
    const float* __restrict__ W1, const float* __restrict__ b1,
    const float* __restrict__ W2, const float* __restrict__ b2,
    const float* __restrict__ Wr, const float* __restrict__ br,
    const float* __restrict__ Ww, const float* __restrict__ bw,
    const float* __restrict__ Wo, const float* __restrict__ bo,
    const float* __restrict__ init_read,
    const float* __restrict__ mem0,
    float* __restrict__ out)
{
    extern __shared__ char smraw[];
    SM& s = *reinterpret_cast<SM*>(smraw);

    const int tid  = threadIdx.x;
    const int b0   = blockIdx.x * BT;
    const int wid  = tid >> 5, lane = tid & 31;

    // ---- init: mem slice from mem0, transposed read from init_read ----
    {
        const float4* src = (const float4*)(mem0 + (size_t)b0 * Nd * Vd);
        float4*       dst = (float4*)(g_mem + (size_t)b0 * Nd * Vd);
        for (int i = tid; i < BT * Nd * Vd / 4; i += NTH) dst[i] = src[i];
        if (tid < BT * Vd / 4) {
            int r = tid >> 6, c4 = tid & 63;
            float4 v = __ldg((const float4*)(init_read + (size_t)(b0 + r) * Vd) + c4);
            ((float*)(s.ciT + Ed + c4 * 4 + 0))[r] = v.x;
            ((float*)(s.ciT + Ed + c4 * 4 + 1))[r] = v.y;
            ((float*)(s.ciT + Ed + c4 * 4 + 2))[r] = v.z;
            ((float*)(s.ciT + Ed + c4 * 4 + 3))[r] = v.w;
        }
    }
    __syncthreads();

    for (int t = 0; t < Td; t++) {
        // ---- stage x_t transposed into ciT[0..Ed) ----
        if (tid < BT * Ed / 4) {
            int r = tid >> 6, c4 = tid & 63;
            float4 v = __ldg((const float4*)(x + ((size_t)t * Bd + b0 + r) * Ed) + c4);
            ((float*)(s.ciT + c4 * 4 + 0))[r] = v.x;
            ((float*)(s.ciT + c4 * 4 + 1))[r] = v.y;
            ((float*)(s.ciT + c4 * 4 + 2))[r] = v.z;
            ((float*)(s.ciT + c4 * 4 + 3))[r] = v.w;
        }
        __syncthreads();

        // h = relu(ci @ W1 + b1) -> hT
        gemm_main<Ed + Vd, Hd>(s.ciT, W1, b1, s.scratch);
        gemm_combine<Hd, NTH / (Hd / 4), true, 1>(s.scratch, nullptr, s.hT, 0);
        __syncthreads();

        // co = h @ W2 + b2 -> woT[0..Cd)
        gemm_main<Hd, Cd>(s.hT, W2, b2, s.scratch);
        gemm_combine<Cd, NTH / (Cd / 4), false, 1>(s.scratch, nullptr, s.woT, 0);
        __syncthreads();

        // k = co @ Wr + br -> row-major s.k
        gemm_main<Cd, Vd>(s.woT, Wr, br, s.scratch);
        gemm_combine<Vd, NTH / (Vd / 4), false, 0>(s.scratch, &s.k[0][0], nullptr, 0);
        __syncthreads();

        // o = co @ Ww + bw -> row-major s.o
        gemm_main<Cd, 2 * Vd>(s.woT, Ww, bw, s.scratch);
        gemm_combine<2 * Vd, NTH / (2 * Vd / 4), false, 0>(s.scratch, &s.o[0][0], nullptr, 0);
        __syncthreads();

        // ---- key norms: warps 0..3 -> kn, warps 4..7 -> kwn ----
        if (wid < BT) {
            float s2 = 0.f;
            for (int i = lane; i < Vd; i += 32) { float v = s.k[wid][i]; s2 = fmaf(v, v, s2); }
            s2 = wsum(s2);
            if (!lane) s.kn[wid] = fmaxf(sqrtf(s2), EPSf);
        } else if (wid < 2 * BT) {
            int r = wid - BT;
            float s2 = 0.f;
            for (int i = lane; i < Vd; i += 32) { float v = s.o[r][i]; s2 = fmaf(v, v, s2); }
            s2 = wsum(s2);
            if (!lane) s.kwn[r] = fmaxf(sqrtf(s2), EPSf);
        }
        __syncthreads();

        // ---- addressing pass: one mem read -> both dots + mem norms (32 warps) ----
        for (int task = wid; task < BT * Nd; task += NWARP) {
            int r = task >> 7, n = task & (Nd - 1);
            const float4* m4 = (const float4*)(g_mem + ((size_t)(b0 + r) * Nd + n) * Vd);
            const float4* k4 = (const float4*)s.k[r];
            const float4* q4 = (const float4*)s.o[r];   // kw = o[:, :V]
            float dk = 0.f, dw = 0.f, nn = 0.f;
            #pragma unroll
            for (int c = lane; c < Vd / 4; c += 32) {
                float4 m = m4[c]; float4 a = k4[c]; float4 b = q4[c];
                dk = fmaf(m.x, a.x, fmaf(m.y, a.y, fmaf(m.z, a.z, fmaf(m.w, a.w, dk))));
                dw = fmaf(m.x, b.x, fmaf(m.y, b.y, fmaf(m.z, b.z, fmaf(m.w, b.w, dw))));
                nn = fmaf(m.x, m.x, fmaf(m.y, m.y, fmaf(m.z, m.z, fmaf(m.w, m.w, nn))));
            }
            dk = wsum(dk); dw = wsum(dw); nn = wsum(nn);
            if (!lane) {
                float mn = fmaxf(sqrtf(nn), EPSf);
                s.w [r][n] = dk / (s.kn [r] * mn);
                s.ww[r][n] = dw / (s.kwn[r] * mn);
            }
        }
        __syncthreads();

        // ---- softmax in-place: warps 0..3 -> w rows, 4..7 -> ww rows ----
        if (wid < 2 * BT) {
            float* rowp = (wid < BT) ? s.w[wid] : s.ww[wid - BT];
            float v0 = rowp[lane], v1 = rowp[lane + 32], v2 = rowp[lane + 64], v3 = rowp[lane + 96];
            float mx = wmax(fmaxf(fmaxf(v0, v1), fmaxf(v2, v3)));
            float e0 = __expf(v0 - mx), e1 = __expf(v1 - mx), e2 = __expf(v2 - mx), e3 = __expf(v3 - mx);
            float sm = wsum(e0 + e1 + e2 + e3);
            float inv = 1.f / sm;
            rowp[lane] = e0 * inv; rowp[lane + 32] = e1 * inv;
            rowp[lane + 64] = e2 * inv; rowp[lane + 96] = e3 * inv;
        }
        __syncthreads();

        // ---- fused r readout (old mem) + mem update, split over 4 n-quarters ----
        {
            int nh = tid >> 8;              // n-quarter: 0..3
            int r  = (tid >> 6) & 3;        // batch row
            int v4 = tid & 63;              // float4 column
            float4* mb = (float4*)(g_mem + (size_t)(b0 + r) * Nd * Vd) + v4;
            float4 vv = ((const float4*)(s.o[r] + Vd))[v4];   // v = o[:, V:]
            float4 ra = make_float4(0.f, 0.f, 0.f, 0.f);
            const int n0 = nh * (Nd / 4);
            #pragma unroll 4
            for (int j = 0; j < Nd / 4; j++) {
                int n = n0 + j;
                float4 m = mb[(size_t)n * (Vd / 4)];
                float wn = s.w[r][n], wwn = s.ww[r][n];
                ra.x = fmaf(wn, m.x, ra.x); ra.y = fmaf(wn, m.y, ra.y);
                ra.z = fmaf(wn, m.z, ra.z); ra.w = fmaf(wn, m.w, ra.w);
                m.x = fmaf(wwn, vv.x, m.x); m.y = fmaf(wwn, vv.y, m.y);
                m.z = fmaf(wwn, vv.z, m.z); m.w = fmaf(wwn, vv.w, m.w);
                mb[(size_t)n * (Vd / 4)] = m;
            }
            s.scratch[(nh * BT + r) * 64 + v4] = ra;
        }
        __syncthreads();

        // combine readout quarters -> transposed r into woT[Cd..] and ciT[Ed..]
        if (tid < BT * Vd / 4) {
            int r = tid >> 6, c4 = tid & 63;
            float4 p0 = s.scratch[(0 * BT + r) * 64 + c4];
            float4 p1 = s.scratch[(1 * BT + r) * 64 + c4];
            float4 p2 = s.scratch[(2 * BT + r) * 64 + c4];
            float4 p3 = s.scratch[(3 * BT + r) * 64 + c4];
            float4 rv = make_float4(p0.x + p1.x + p2.x + p3.x,
                                    p0.y + p1.y + p2.y + p3.y,
                                    p0.z + p1.z + p2.z + p3.z,
                                    p0.w + p1.w + p2.w + p3.w);
            ((float*)(s.woT + Cd + c4 * 4 + 0))[r] = rv.x;
            ((float*)(s.woT + Cd + c4 * 4 + 1))[r] = rv.y;
            ((float*)(s.woT + Cd + c4 * 4 + 2))[r] = rv.z;
            ((float*)(s.woT + Cd + c4 * 4 + 3))[r] = rv.w;
            ((float*)(s.ciT + Ed + c4 * 4 + 0))[r] = rv.x;
            ((float*)(s.ciT + Ed + c4 * 4 + 1))[r] = rv.y;
            ((float*)(s.ciT + Ed + c4 * 4 + 2))[r] = rv.z;
            ((float*)(s.ciT + Ed + c4 * 4 + 3))[r] = rv.w;
        }
        __syncthreads();

        // out = [co | r] @ Wo + bo -> global
        gemm_main<Cd + Vd, Od>(s.woT, Wo, bo, s.scratch);
        gemm_combine<Od, NTH / (Od / 4), false, 2>(s.scratch,
                                                   out + ((size_t)t * Bd + b0) * Od,
                                                   nullptr, (size_t)Od);
        __syncthreads();
    }
}

extern "C" void kernel_launch(void* const* d_in, const int* in_sizes, int n_in,
                              void* d_out, int out_size)
{
    (void)in_sizes; (void)n_in; (void)out_size;
    const float* x         = (const float*)d_in[0];
    const float* W1        = (const float*)d_in[1];
    const float* b1        = (const float*)d_in[2];
    const float* W2        = (const float*)d_in[3];
    const float* b2        = (const float*)d_in[4];
    const float* Wr        = (const float*)d_in[5];
    const float* br        = (const float*)d_in[6];
    const float* Ww        = (const float*)d_in[7];
    const float* bw        = (const float*)d_in[8];
    const float* Wo        = (const float*)d_in[9];
    const float* bo        = (const float*)d_in[10];
    const float* init_read = (const float*)d_in[11];
    const float* mem0      = (const float*)d_in[12];
    float* out = (float*)d_out;

    int smem = (int)sizeof(SM);
    cudaFuncSetAttribute(ntm_kernel, cudaFuncAttributeMaxDynamicSharedMemorySize, smem);
    ntm_kernel<<<NCTA, NTH, smem>>>(x, W1, b1, W2, b2, Wr, br, Ww, bw, Wo, bo,
                                    init_read, mem0, out);
}

// round 8
// speedup vs baseline: 2.5951x; 1.1907x over previous
#include <cuda_runtime.h>

// Problem dims
#define Td 256
#define Bd 512
#define Ed 256
#define Hd 256
#define Cd 256
#define Nd 128
#define Vd 256
#define Od 256
#define EPSf 1e-8f

#define BT   4            // batch rows per CTA
#define NCTA (Bd/BT)      // 128 CTAs
#define NTH  1024         // threads per CTA (32 warps)
#define NWARP (NTH/32)

// 64MB NTM memory state scratch (allowed: __device__ global array)
__device__ float g_mem[(size_t)Bd * Nd * Vd];

// Dynamic smem layout (float4 arrays first for alignment). ~105KB total.
struct SM {
    float4 scratch[16 * BT * 64];  // 64KB: GEMM partials / fused-pass r partials (32KB)
    float4 ciT[Ed + Vd];           // 8KB : transposed [x_t | read]
    float4 hT [Hd];                // 4KB : transposed hidden
    float4 woT[Cd + Vd];           // 8KB : transposed [co | r]
    float  k [BT][Vd];             // 4KB : read key (row-major)
    float  o [BT][2 * Vd];         // 8KB : [kw | v] (row-major)
    float  ww[BT][Nd];             // 2KB : raw write-address scores
    float  wwprev[BT][Nd];         // 2KB : normalized write weights (pending update)
    float  vprev[BT][Vd];          // 4KB : pending update value vector
    float  pM[BT][8], pZ[BT][8];   // online-softmax partials (per r, per warp-group j)
    float  coef[BT][8];
    float  invZ[BT];
    float  kn[BT], kwn[BT];
};

__device__ __forceinline__ float wsum(float v) {
    #pragma unroll
    for (int o = 16; o; o >>= 1) v += __shfl_xor_sync(0xffffffffu, v, o);
    return v;
}
__device__ __forceinline__ float wmax(float v) {
    #pragma unroll
    for (int o = 16; o; o >>= 1) v = fmaxf(v, __shfl_xor_sync(0xffffffffu, v, o));
    return v;
}

// Register-tiled K-sliced GEMM main pass (unchanged from R6).
template<int KC, int NC>
__device__ __forceinline__ void gemm_main(const float4* __restrict__ actT,
                                          const float* __restrict__ W,
                                          const float* __restrict__ bias,
                                          float4* __restrict__ scratch)
{
    constexpr int CG = NC / 4;
    constexpr int KS = NTH / CG;
    constexpr int KL = KC / KS;
    const int tid = threadIdx.x;
    const int ks = tid / CG;
    const int cg = tid - ks * CG;

    const float4* wp = (const float4*)(W + (size_t)(ks * KL) * NC) + cg;
    const float4* ap = actT + ks * KL;

    float4 a0, a1, a2, a3;
    if (ks == 0) { float4 b = __ldg((const float4*)bias + cg); a0 = a1 = a2 = a3 = b; }
    else { a0 = a1 = a2 = a3 = make_float4(0.f, 0.f, 0.f, 0.f); }

    #pragma unroll 4
    for (int kk = 0; kk < KL; kk++) {
        float4 av = ap[kk];
        float4 wv = __ldg(wp + (size_t)kk * (NC / 4));
        a0.x = fmaf(av.x, wv.x, a0.x); a0.y = fmaf(av.x, wv.y, a0.y);
        a0.z = fmaf(av.x, wv.z, a0.z); a0.w = fmaf(av.x, wv.w, a0.w);
        a1.x = fmaf(av.y, wv.x, a1.x); a1.y = fmaf(av.y, wv.y, a1.y);
        a1.z = fmaf(av.y, wv.z, a1.z); a1.w = fmaf(av.y, wv.w, a1.w);
        a2.x = fmaf(av.z, wv.x, a2.x); a2.y = fmaf(av.z, wv.y, a2.y);
        a2.z = fmaf(av.z, wv.z, a2.z); a2.w = fmaf(av.z, wv.w, a2.w);
        a3.x = fmaf(av.w, wv.x, a3.x); a3.y = fmaf(av.w, wv.y, a3.y);
        a3.z = fmaf(av.w, wv.z, a3.z); a3.w = fmaf(av.w, wv.w, a3.w);
    }
    scratch[(ks * BT + 0) * CG + cg] = a0;
    scratch[(ks * BT + 1) * CG + cg] = a1;
    scratch[(ks * BT + 2) * CG + cg] = a2;
    scratch[(ks * BT + 3) * CG + cg] = a3;
    __syncthreads();
}

// Combine K-slice partials. MODE 0: row-major smem. MODE 1: transposed smem.
// MODE 2: row-major global. Caller must __syncthreads() after.
template<int NC, int KS, bool RELU, int MODE>
__device__ __forceinline__ void gemm_combine(const float4* __restrict__ scratch,
                                             float* __restrict__ dst,
                                             float4* __restrict__ dstT,
                                             size_t rstride)
{
    constexpr int CG = NC / 4;
    constexpr int TASKS = BT * CG;
    const int tid = threadIdx.x;
    if (tid < TASKS) {
        const int row = tid / CG, cg = tid - row * CG;
        float4 v = scratch[row * CG + cg];
        #pragma unroll
        for (int ks = 1; ks < KS; ks++) {
            float4 p = scratch[(ks * BT + row) * CG + cg];
            v.x += p.x; v.y += p.y; v.z += p.z; v.w += p.w;
        }
        if (RELU) {
            v.x = fmaxf(v.x, 0.f); v.y = fmaxf(v.y, 0.f);
            v.z = fmaxf(v.z, 0.f); v.w = fmaxf(v.w, 0.f);
        }
        if (MODE == 0) {
            *(float4*)(dst + row * NC + cg * 4) = v;
        } else if (MODE == 1) {
            ((float*)(dstT + cg * 4 + 0))[row] = v.x;
            ((float*)(dstT + cg * 4 + 1))[row] = v.y;
            ((float*)(dstT + cg * 4 + 2))[row] = v.z;
            ((float*)(dstT + cg * 4 + 3))[row] = v.w;
        } else {
            *(float4*)(dst + (size_t)row * rstride + cg * 4) = v;
        }
    }
}

__global__ void __launch_bounds__(NTH, 1) ntm_kernel(
    const float* __restrict__ x,
    const float* __restrict__ W1, const float* __restrict__ b1,
    const float* __restrict__ W2, const float* __restrict__ b2,
    const float* __restrict__ Wr, const float* __restrict__ br,
    const float* __restrict__ Ww, const float* __restrict__ bw,
    const float* __restrict__ Wo, const float* __restrict__ bo,
    const float* __restrict__ init_read,
    const float* __restrict__ mem0,
    float* __restrict__ out)
{
    extern __shared__ char smraw[];
    SM& s = *reinterpret_cast<SM*>(smraw);

    const int tid  = threadIdx.x;
    const int b0   = blockIdx.x * BT;
    const int wid  = tid >> 5, lane = tid & 31;

    // ---- init: mem slice, zero pending update, transposed init_read ----
    {
        const float4* src = (const float4*)(mem0 + (size_t)b0 * Nd * Vd);
        float4*       dst = (float4*)(g_mem + (size_t)b0 * Nd * Vd);
        for (int i = tid; i < BT * Nd * Vd / 4; i += NTH) dst[i] = src[i];
        if (tid < BT * Nd) { ((float*)s.wwprev)[tid] = 0.f; }
        for (int i = tid; i < BT * Vd; i += NTH) ((float*)s.vprev)[i] = 0.f;
        if (tid < BT * Vd / 4) {
            int r = tid >> 6, c4 = tid & 63;
            float4 v = __ldg((const float4*)(init_read + (size_t)(b0 + r) * Vd) + c4);
            ((float*)(s.ciT + Ed + c4 * 4 + 0))[r] = v.x;
            ((float*)(s.ciT + Ed + c4 * 4 + 1))[r] = v.y;
            ((float*)(s.ciT + Ed + c4 * 4 + 2))[r] = v.z;
            ((float*)(s.ciT + Ed + c4 * 4 + 3))[r] = v.w;
        }
    }
    __syncthreads();

    for (int t = 0; t < Td; t++) {
        // ---- stage x_t transposed into ciT[0..Ed) ----
        if (tid < BT * Ed / 4) {
            int r = tid >> 6, c4 = tid & 63;
            float4 v = __ldg((const float4*)(x + ((size_t)t * Bd + b0 + r) * Ed) + c4);
            ((float*)(s.ciT + c4 * 4 + 0))[r] = v.x;
            ((float*)(s.ciT + c4 * 4 + 1))[r] = v.y;
            ((float*)(s.ciT + c4 * 4 + 2))[r] = v.z;
            ((float*)(s.ciT + c4 * 4 + 3))[r] = v.w;
        }
        __syncthreads();

        // h = relu(ci @ W1 + b1) -> hT
        gemm_main<Ed + Vd, Hd>(s.ciT, W1, b1, s.scratch);
        gemm_combine<Hd, NTH / (Hd / 4), true, 1>(s.scratch, nullptr, s.hT, 0);
        __syncthreads();

        // co = h @ W2 + b2 -> woT[0..Cd)
        gemm_main<Hd, Cd>(s.hT, W2, b2, s.scratch);
        gemm_combine<Cd, NTH / (Cd / 4), false, 1>(s.scratch, nullptr, s.woT, 0);
        __syncthreads();

        // k = co @ Wr + br -> row-major s.k
        gemm_main<Cd, Vd>(s.woT, Wr, br, s.scratch);
        gemm_combine<Vd, NTH / (Vd / 4), false, 0>(s.scratch, &s.k[0][0], nullptr, 0);
        __syncthreads();

        // o = co @ Ww + bw -> row-major s.o
        gemm_main<Cd, 2 * Vd>(s.woT, Ww, bw, s.scratch);
        gemm_combine<2 * Vd, NTH / (2 * Vd / 4), false, 0>(s.scratch, &s.o[0][0], nullptr, 0);
        __syncthreads();

        // ---- key norms: warps 0..3 -> kn, warps 4..7 -> kwn ----
        if (wid < BT) {
            float s2 = 0.f;
            for (int i = lane; i < Vd; i += 32) { float v = s.k[wid][i]; s2 = fmaf(v, v, s2); }
            s2 = wsum(s2);
            if (!lane) s.kn[wid] = fmaxf(sqrtf(s2), EPSf);
        } else if (wid < 2 * BT) {
            int r = wid - BT;
            float s2 = 0.f;
            for (int i = lane; i < Vd; i += 32) { float v = s.o[r][i]; s2 = fmaf(v, v, s2); }
            s2 = wsum(s2);
            if (!lane) s.kwn[r] = fmaxf(sqrtf(s2), EPSf);
        }
        __syncthreads();

        // ==== FUSED pass: deferred mem update + dots + online-softmax readout ====
        // warp w: r = w>>3, j = w&7; slots n = j + 8i. ONE mem read + ONE write.
        {
            const int r = wid >> 3, j = wid & 7;
            const float4* k4 = (const float4*)s.k[r];
            const float4* q4 = (const float4*)s.o[r];        // kw = o[:, :V]
            const float4* v4 = (const float4*)s.vprev[r];
            float4 kv0 = k4[lane], kv1 = k4[lane + 32];
            float4 vv0 = v4[lane], vv1 = v4[lane + 32];
            const float knr = s.kn[r], kwnr = s.kwn[r];
            float M = -1e30f, Z = 0.f;
            float4 a0 = make_float4(0.f, 0.f, 0.f, 0.f), a1 = a0;
            float4* gm = (float4*)(g_mem + (size_t)(b0 + r) * Nd * Vd);

            #pragma unroll 2
            for (int i = 0; i < Nd / 8; i++) {
                const int n = j + 8 * i;
                float4* mp = gm + (size_t)n * (Vd / 4);
                float4 m0 = mp[lane], m1 = mp[lane + 32];
                float wp = s.wwprev[r][n];
                m0.x = fmaf(wp, vv0.x, m0.x); m0.y = fmaf(wp, vv0.y, m0.y);
                m0.z = fmaf(wp, vv0.z, m0.z); m0.w = fmaf(wp, vv0.w, m0.w);
                m1.x = fmaf(wp, vv1.x, m1.x); m1.y = fmaf(wp, vv1.y, m1.y);
                m1.z = fmaf(wp, vv1.z, m1.z); m1.w = fmaf(wp, vv1.w, m1.w);
                mp[lane] = m0; mp[lane + 32] = m1;

                float4 q0 = q4[lane], q1 = q4[lane + 32];
                float dk = 0.f, dw = 0.f, nn = 0.f;
                dk = fmaf(m0.x, kv0.x, fmaf(m0.y, kv0.y, fmaf(m0.z, kv0.z, fmaf(m0.w, kv0.w, dk))));
                dk = fmaf(m1.x, kv1.x, fmaf(m1.y, kv1.y, fmaf(m1.z, kv1.z, fmaf(m1.w, kv1.w, dk))));
                dw = fmaf(m0.x, q0.x, fmaf(m0.y, q0.y, fmaf(m0.z, q0.z, fmaf(m0.w, q0.w, dw))));
                dw = fmaf(m1.x, q1.x, fmaf(m1.y, q1.y, fmaf(m1.z, q1.z, fmaf(m1.w, q1.w, dw))));
                nn = fmaf(m0.x, m0.x, fmaf(m0.y, m0.y, fmaf(m0.z, m0.z, fmaf(m0.w, m0.w, nn))));
                nn = fmaf(m1.x, m1.x, fmaf(m1.y, m1.y, fmaf(m1.z, m1.z, fmaf(m1.w, m1.w, nn))));
                dk = wsum(dk); dw = wsum(dw); nn = wsum(nn);

                float mn = fmaxf(sqrtf(nn), EPSf);
                float sk = dk / (knr * mn);
                float sw = dw / (kwnr * mn);
                if (!lane) s.ww[r][n] = sw;

                float nM = fmaxf(M, sk);
                float sc = __expf(M - nM);
                float e  = __expf(sk - nM);
                Z = fmaf(Z, sc, e);
                a0.x = fmaf(a0.x, sc, e * m0.x); a0.y = fmaf(a0.y, sc, e * m0.y);
                a0.z = fmaf(a0.z, sc, e * m0.z); a0.w = fmaf(a0.w, sc, e * m0.w);
                a1.x = fmaf(a1.x, sc, e * m1.x); a1.y = fmaf(a1.y, sc, e * m1.y);
                a1.z = fmaf(a1.z, sc, e * m1.z); a1.w = fmaf(a1.w, sc, e * m1.w);
                M = nM;
            }
            s.scratch[(r * 8 + j) * 64 + lane]      = a0;
            s.scratch[(r * 8 + j) * 64 + lane + 32] = a1;
            if (!lane) { s.pM[r][j] = M; s.pZ[r][j] = Z; }
        }
        __syncthreads();

        // ---- merge online-softmax partial scales (warp 0) ----
        if (wid == 0) {
            int r = lane >> 3, j = lane & 7;
            float m = s.pM[r][j];
            float mm = m;
            mm = fmaxf(mm, __shfl_xor_sync(0xffffffffu, mm, 1));
            mm = fmaxf(mm, __shfl_xor_sync(0xffffffffu, mm, 2));
            mm = fmaxf(mm, __shfl_xor_sync(0xffffffffu, mm, 4));
            float cf = __expf(m - mm);
            float zc = cf * s.pZ[r][j];
            float zs = zc;
            zs += __shfl_xor_sync(0xffffffffu, zs, 1);
            zs += __shfl_xor_sync(0xffffffffu, zs, 2);
            zs += __shfl_xor_sync(0xffffffffu, zs, 4);
            s.coef[r][j] = cf;
            if (j == 0) s.invZ[r] = 1.f / zs;
        }
        __syncthreads();

        // ---- parallel: r-vector combine | ww softmax -> wwprev | v -> vprev ----
        if (tid < BT * Vd / 4) {
            // combine 8 partials -> r, write transposed into woT[Cd..] and ciT[Ed..]
            int r = tid >> 6, c4 = tid & 63;
            float4 acc = make_float4(0.f, 0.f, 0.f, 0.f);
            #pragma unroll
            for (int j = 0; j < 8; j++) {
                float cf = s.coef[r][j];
                float4 p = s.scratch[(r * 8 + j) * 64 + c4];
                acc.x = fmaf(cf, p.x, acc.x); acc.y = fmaf(cf, p.y, acc.y);
                acc.z = fmaf(cf, p.z, acc.z); acc.w = fmaf(cf, p.w, acc.w);
            }
            float iz = s.invZ[r];
            acc.x *= iz; acc.y *= iz; acc.z *= iz; acc.w *= iz;
            ((float*)(s.woT + Cd + c4 * 4 + 0))[r] = acc.x;
            ((float*)(s.woT + Cd + c4 * 4 + 1))[r] = acc.y;
            ((float*)(s.woT + Cd + c4 * 4 + 2))[r] = acc.z;
            ((float*)(s.woT + Cd + c4 * 4 + 3))[r] = acc.w;
            ((float*)(s.ciT + Ed + c4 * 4 + 0))[r] = acc.x;
            ((float*)(s.ciT + Ed + c4 * 4 + 1))[r] = acc.y;
            ((float*)(s.ciT + Ed + c4 * 4 + 2))[r] = acc.z;
            ((float*)(s.ciT + Ed + c4 * 4 + 3))[r] = acc.w;
        } else if (wid >= 16 && wid < 16 + BT) {
            // softmax over write scores -> normalized weights for next step
            int r = wid - 16;
            float* rowp = s.ww[r];
            float v0 = rowp[lane], v1 = rowp[lane + 32], v2 = rowp[lane + 64], v3 = rowp[lane + 96];
            float mx = wmax(fmaxf(fmaxf(v0, v1), fmaxf(v2, v3)));
            float e0 = __expf(v0 - mx), e1 = __expf(v1 - mx), e2 = __expf(v2 - mx), e3 = __expf(v3 - mx);
            float sm = wsum(e0 + e1 + e2 + e3);
            float inv = 1.f / sm;
            s.wwprev[r][lane]      = e0 * inv;
            s.wwprev[r][lane + 32] = e1 * inv;
            s.wwprev[r][lane + 64] = e2 * inv;
            s.wwprev[r][lane + 96] = e3 * inv;
        } else if (wid >= 24) {
            // copy v = o[:, V:] -> vprev (pending update value)
            int i = tid - 24 * 32;              // 0..255
            int r = i >> 6, c4 = i & 63;
            ((float4*)s.vprev[r])[c4] = ((const float4*)(s.o[r] + Vd))[c4];
        }
        __syncthreads();

        // out = [co | r] @ Wo + bo -> global
        gemm_main<Cd + Vd, Od>(s.woT, Wo, bo, s.scratch);
        gemm_combine<Od, NTH / (Od / 4), false, 2>(s.scratch,
                                                   out + ((size_t)t * Bd + b0) * Od,
                                                   nullptr, (size_t)Od);
        __syncthreads();
    }
}

extern "C" void kernel_launch(void* const* d_in, const int* in_sizes, int n_in,
                              void* d_out, int out_size)
{
    (void)in_sizes; (void)n_in; (void)out_size;
    const float* x         = (const float*)d_in[0];
    const float* W1        = (const float*)d_in[1];
    const float* b1        = (const float*)d_in[2];
    const float* W2        = (const float*)d_in[3];
    const float* b2        = (const float*)d_in[4];
    const float* Wr        = (const float*)d_in[5];
    const float* br        = (const float*)d_in[6];
    const float* Ww        = (const float*)d_in[7];
    const float* bw        = (const float*)d_in[8];
    const float* Wo        = (const float*)d_in[9];
    const float* bo        = (const float*)d_in[10];
    const float* init_read = (const float*)d_in[11];
    const float* mem0      = (const float*)d_in[12];
    float* out = (float*)d_out;

    int smem = (int)sizeof(SM);
    cudaFuncSetAttribute(ntm_kernel, cudaFuncAttributeMaxDynamicSharedMemorySize, smem);
    ntm_kernel<<<NCTA, NTH, smem>>>(x, W1, b1, W2, b2, Wr, br, Ww, bw, Wo, bo,
                                    init_read, mem0, out);
}

// round 9
// speedup vs baseline: 2.8111x; 1.0832x over previous
#include <cuda_runtime.h>

// Problem dims
#define Td 256
#define Bd 512
#define Ed 256
#define Hd 256
#define Cd 256
#define Nd 128
#define Vd 256
#define Od 256
#define EPSf 1e-8f

#define BT   4            // batch rows per CTA
#define NCTA (Bd/BT)      // 128 CTAs
#define NTH  1024         // threads per CTA (32 warps)
#define NWARP (NTH/32)

typedef unsigned long long u64;

// Packed f32x2 ops (sm_103a): 2 fp32 MACs per issue slot on the fma pipe.
#define FMA2(d, a, b, c) \
    asm("fma.rn.f32x2 %0, %1, %2, %3;" : "=l"(d) : "l"(a), "l"(b), "l"(c))
#define MUL2(d, a, b) \
    asm("mul.rn.f32x2 %0, %1, %2;" : "=l"(d) : "l"(a), "l"(b))
#define PK2(d, lo, hi) \
    asm("mov.b64 %0, {%1, %2};" : "=l"(d) : "f"(lo), "f"(hi))
#define UPK2(lo, hi, s) \
    asm("mov.b64 {%0, %1}, %2;" : "=f"(lo), "=f"(hi) : "l"(s))

// 64MB NTM memory state scratch (allowed: __device__ global array)
__device__ float g_mem[(size_t)Bd * Nd * Vd];

// Dynamic smem layout (float4 arrays first for alignment). ~105KB total.
struct SM {
    float4 scratch[16 * BT * 64];  // 64KB: GEMM partials / fused-pass r partials
    float4 ciT[Ed + Vd];           // 8KB : transposed [x_t | read]
    float4 hT [Hd];                // 4KB : transposed hidden
    float4 woT[Cd + Vd];           // 8KB : transposed [co | r]
    float  k [BT][Vd];             // 4KB : read key (row-major)
    float  o [BT][2 * Vd];         // 8KB : [kw | v] (row-major)
    float  ww[BT][Nd];             // 2KB : raw write-address scores
    float  wwprev[BT][Nd];         // 2KB : normalized write weights (pending update)
    float  vprev[BT][Vd];          // 4KB : pending update value vector
    float  pM[BT][8], pZ[BT][8];   // online-softmax partials
    float  coef[BT][8];
    float  invZ[BT];
    float  kn[BT], kwn[BT];
};

__device__ __forceinline__ float wsum(float v) {
    #pragma unroll
    for (int o = 16; o; o >>= 1) v += __shfl_xor_sync(0xffffffffu, v, o);
    return v;
}
__device__ __forceinline__ float wmax(float v) {
    #pragma unroll
    for (int o = 16; o; o >>= 1) v = fmaxf(v, __shfl_xor_sync(0xffffffffu, v, o));
    return v;
}

// Register-tiled K-sliced GEMM main pass, f32x2 accumulators.
// actT[k] = float4 of the 4 batch rows' activation at k.
// Weight LDG.128 reinterpreted as two f32x2 operands (zero pack cost).
// Per 16 MACs: 8 FFMA2 + 4 packs. Partials -> scratch. Ends with __syncthreads().
template<int KC, int NC>
__device__ __forceinline__ void gemm_main(const float4* __restrict__ actT,
                                          const float* __restrict__ W,
                                          const float* __restrict__ bias,
                                          float4* __restrict__ scratch)
{
    constexpr int CG = NC / 4;
    constexpr int KS = NTH / CG;
    constexpr int KL = KC / KS;
    const int tid = threadIdx.x;
    const int ks = tid / CG;
    const int cg = tid - ks * CG;

    // weight pointer in 16B units: row (ks*KL + kk), col-group cg
    const ulonglong2* wq =
        (const ulonglong2*)(W + (size_t)(ks * KL) * NC) + cg;
    const float4* ap = actT + ks * KL;

    u64 a01[BT], a23[BT];   // acc[row] cols (0,1) and (2,3) as f32x2
    if (ks == 0) {
        ulonglong2 b = __ldg((const ulonglong2*)bias + cg);
        #pragma unroll
        for (int r = 0; r < BT; r++) { a01[r] = b.x; a23[r] = b.y; }
    } else {
        #pragma unroll
        for (int r = 0; r < BT; r++) { a01[r] = 0ull; a23[r] = 0ull; }
    }

    #pragma unroll 4
    for (int kk = 0; kk < KL; kk++) {
        float4 av = ap[kk];                                // LDS.128 broadcast
        ulonglong2 wv = __ldg(wq + (size_t)kk * (NC / 4)); // LDG.128 = 2 x f32x2
        u64 aa;
        PK2(aa, av.x, av.x);
        FMA2(a01[0], aa, wv.x, a01[0]); FMA2(a23[0], aa, wv.y, a23[0]);
        PK2(aa, av.y, av.y);
        FMA2(a01[1], aa, wv.x, a01[1]); FMA2(a23[1], aa, wv.y, a23[1]);
        PK2(aa, av.z, av.z);
        FMA2(a01[2], aa, wv.x, a01[2]); FMA2(a23[2], aa, wv.y, a23[2]);
        PK2(aa, av.w, av.w);
        FMA2(a01[3], aa, wv.x, a01[3]); FMA2(a23[3], aa, wv.y, a23[3]);
    }
    #pragma unroll
    for (int r = 0; r < BT; r++)
        ((ulonglong2*)scratch)[(ks * BT + r) * CG + cg] =
            make_ulonglong2(a01[r], a23[r]);
    __syncthreads();
}

// Combine K-slice partials. MODE 0: row-major smem. MODE 1: transposed smem.
// MODE 2: row-major global. Caller must __syncthreads() after.
template<int NC, int KS, bool RELU, int MODE>
__device__ __forceinline__ void gemm_combine(const float4* __restrict__ scratch,
                                             float* __restrict__ dst,
                                             float4* __restrict__ dstT,
                                             size_t rstride)
{
    constexpr int CG = NC / 4;
    constexpr int TASKS = BT * CG;
    const int tid = threadIdx.x;
    if (tid < TASKS) {
        const int row = tid / CG, cg = tid - row * CG;
        float4 v = scratch[row * CG + cg];
        #pragma unroll
        for (int ks = 1; ks < KS; ks++) {
            float4 p = scratch[(ks * BT + row) * CG + cg];
            v.x += p.x; v.y += p.y; v.z += p.z; v.w += p.w;
        }
        if (RELU) {
            v.x = fmaxf(v.x, 0.f); v.y = fmaxf(v.y, 0.f);
            v.z = fmaxf(v.z, 0.f); v.w = fmaxf(v.w, 0.f);
        }
        if (MODE == 0) {
            *(float4*)(dst + row * NC + cg * 4) = v;
        } else if (MODE == 1) {
            ((float*)(dstT + cg * 4 + 0))[row] = v.x;
            ((float*)(dstT + cg * 4 + 1))[row] = v.y;
            ((float*)(dstT + cg * 4 + 2))[row] = v.z;
            ((float*)(dstT + cg * 4 + 3))[row] = v.w;
        } else {
            *(float4*)(dst + (size_t)row * rstride + cg * 4) = v;
        }
    }
}

__global__ void __launch_bounds__(NTH, 1) ntm_kernel(
    const float* __restrict__ x,
    const float* __restrict__ W1, const float* __restrict__ b1,
    const float* __restrict__ W2, const float* __restrict__ b2,
    const float* __restrict__ Wr, const float* __restrict__ br,
    const float* __restrict__ Ww, const float* __restrict__ bw,
    const float* __restrict__ Wo, const float* __restrict__ bo,
    const float* __restrict__ init_read,
    const float* __restrict__ mem0,
    float* __restrict__ out)
{
    extern __shared__ char smraw[];
    SM& s = *reinterpret_cast<SM*>(smraw);

    const int tid  = threadIdx.x;
    const int b0   = blockIdx.x * BT;
    const int wid  = tid >> 5, lane = tid & 31;

    // ---- init: mem slice, zero pending update, transposed init_read ----
    {
        const float4* src = (const float4*)(mem0 + (size_t)b0 * Nd * Vd);
        float4*       dst = (float4*)(g_mem + (size_t)b0 * Nd * Vd);
        for (int i = tid; i < BT * Nd * Vd / 4; i += NTH) dst[i] = src[i];
        if (tid < BT * Nd) { ((float*)s.wwprev)[tid] = 0.f; }
        for (int i = tid; i < BT * Vd; i += NTH) ((float*)s.vprev)[i] = 0.f;
        if (tid < BT * Vd / 4) {
            int r = tid >> 6, c4 = tid & 63;
            float4 v = __ldg((const float4*)(init_read + (size_t)(b0 + r) * Vd) + c4);
            ((float*)(s.ciT + Ed + c4 * 4 + 0))[r] = v.x;
            ((float*)(s.ciT + Ed + c4 * 4 + 1))[r] = v.y;
            ((float*)(s.ciT + Ed + c4 * 4 + 2))[r] = v.z;
            ((float*)(s.ciT + Ed + c4 * 4 + 3))[r] = v.w;
        }
    }
    __syncthreads();

    for (int t = 0; t < Td; t++) {
        // ---- stage x_t transposed into ciT[0..Ed) ----
        if (tid < BT * Ed / 4) {
            int r = tid >> 6, c4 = tid & 63;
            float4 v = __ldg((const float4*)(x + ((size_t)t * Bd + b0 + r) * Ed) + c4);
            ((float*)(s.ciT + c4 * 4 + 0))[r] = v.x;
            ((float*)(s.ciT + c4 * 4 + 1))[r] = v.y;
            ((float*)(s.ciT + c4 * 4 + 2))[r] = v.z;
            ((float*)(s.ciT + c4 * 4 + 3))[r] = v.w;
        }
        __syncthreads();

        // h = relu(ci @ W1 + b1) -> hT
        gemm_main<Ed + Vd, Hd>(s.ciT, W1, b1, s.scratch);
        gemm_combine<Hd, NTH / (Hd / 4), true, 1>(s.scratch, nullptr, s.hT, 0);
        __syncthreads();

        // co = h @ W2 + b2 -> woT[0..Cd)
        gemm_main<Hd, Cd>(s.hT, W2, b2, s.scratch);
        gemm_combine<Cd, NTH / (Cd / 4), false, 1>(s.scratch, nullptr, s.woT, 0);
        __syncthreads();

        // k = co @ Wr + br -> row-major s.k
        gemm_main<Cd, Vd>(s.woT, Wr, br, s.scratch);
        gemm_combine<Vd, NTH / (Vd / 4), false, 0>(s.scratch, &s.k[0][0], nullptr, 0);
        __syncthreads();

        // o = co @ Ww + bw -> row-major s.o
        gemm_main<Cd, 2 * Vd>(s.woT, Ww, bw, s.scratch);
        gemm_combine<2 * Vd, NTH / (2 * Vd / 4), false, 0>(s.scratch, &s.o[0][0], nullptr, 0);
        __syncthreads();

        // ---- key norms: warps 0..3 -> kn, warps 4..7 -> kwn ----
        if (wid < BT) {
            float s2 = 0.f;
            for (int i = lane; i < Vd; i += 32) { float v = s.k[wid][i]; s2 = fmaf(v, v, s2); }
            s2 = wsum(s2);
            if (!lane) s.kn[wid] = fmaxf(sqrtf(s2), EPSf);
        } else if (wid < 2 * BT) {
            int r = wid - BT;
            float s2 = 0.f;
            for (int i = lane; i < Vd; i += 32) { float v = s.o[r][i]; s2 = fmaf(v, v, s2); }
            s2 = wsum(s2);
            if (!lane) s.kwn[r] = fmaxf(sqrtf(s2), EPSf);
        }
        __syncthreads();

        // ==== FUSED pass (f32x2): deferred update + dots + online-softmax readout ====
        // warp w: r = w>>3, j = w&7; slots n = j + 8i. ONE mem read + ONE write.
        {
            const int r = wid >> 3, j = wid & 7;
            const ulonglong2* k2 = (const ulonglong2*)s.k[r];
            const ulonglong2* q2 = (const ulonglong2*)s.o[r];     // kw = o[:, :V]
            const ulonglong2* v2 = (const ulonglong2*)s.vprev[r];
            // hoisted loop-invariant operands (f32x2 pairs)
            ulonglong2 kA = k2[lane], kB = k2[lane + 32];
            ulonglong2 qA = q2[lane], qB = q2[lane + 32];
            ulonglong2 vA = v2[lane], vB = v2[lane + 32];
            const float knr = s.kn[r], kwnr = s.kwn[r];
            float M = -1e30f, Z = 0.f;
            u64 r0 = 0ull, r1 = 0ull, r2 = 0ull, r3 = 0ull;   // readout accumulators
            ulonglong2* gm = (ulonglong2*)(g_mem + (size_t)(b0 + r) * Nd * Vd);

            #pragma unroll 2
            for (int i = 0; i < Nd / 8; i++) {
                const int n = j + 8 * i;
                ulonglong2* mp = gm + (size_t)n * (Vd / 4);
                ulonglong2 m0 = mp[lane], m1 = mp[lane + 32];
                float wp = s.wwprev[r][n];
                u64 wp2; PK2(wp2, wp, wp);
                FMA2(m0.x, wp2, vA.x, m0.x); FMA2(m0.y, wp2, vA.y, m0.y);
                FMA2(m1.x, wp2, vB.x, m1.x); FMA2(m1.y, wp2, vB.y, m1.y);
                mp[lane] = m0; mp[lane + 32] = m1;

                u64 dk2 = 0ull, dw2 = 0ull, nn2 = 0ull;
                FMA2(dk2, m0.x, kA.x, dk2); FMA2(dk2, m0.y, kA.y, dk2);
                FMA2(dk2, m1.x, kB.x, dk2); FMA2(dk2, m1.y, kB.y, dk2);
                FMA2(dw2, m0.x, qA.x, dw2); FMA2(dw2, m0.y, qA.y, dw2);
                FMA2(dw2, m1.x, qB.x, dw2); FMA2(dw2, m1.y, qB.y, dw2);
                FMA2(nn2, m0.x, m0.x, nn2); FMA2(nn2, m0.y, m0.y, nn2);
                FMA2(nn2, m1.x, m1.x, nn2); FMA2(nn2, m1.y, m1.y, nn2);
                float lo, hi, dk, dw, nn;
                UPK2(lo, hi, dk2); dk = lo + hi;
                UPK2(lo, hi, dw2); dw = lo + hi;
                UPK2(lo, hi, nn2); nn = lo + hi;
                dk = wsum(dk); dw = wsum(dw); nn = wsum(nn);

                float mn = fmaxf(sqrtf(nn), EPSf);
                float sk = dk / (knr * mn);
                float sw = dw / (kwnr * mn);
                if (!lane) s.ww[r][n] = sw;

                float nM = fmaxf(M, sk);
                float sc = __expf(M - nM);
                float e  = __expf(sk - nM);
                Z = fmaf(Z, sc, e);
                u64 sc2, e2, tt;
                PK2(sc2, sc, sc); PK2(e2, e, e);
                MUL2(tt, e2, m0.x); FMA2(r0, r0, sc2, tt);
                MUL2(tt, e2, m0.y); FMA2(r1, r1, sc2, tt);
                MUL2(tt, e2, m1.x); FMA2(r2, r2, sc2, tt);
                MUL2(tt, e2, m1.y); FMA2(r3, r3, sc2, tt);
                M = nM;
            }
            ((ulonglong2*)s.scratch)[(r * 8 + j) * 64 + lane]      = make_ulonglong2(r0, r1);
            ((ulonglong2*)s.scratch)[(r * 8 + j) * 64 + lane + 32] = make_ulonglong2(r2, r3);
            if (!lane) { s.pM[r][j] = M; s.pZ[r][j] = Z; }
        }
        __syncthreads();

        // ---- merge online-softmax partial scales (warp 0) ----
        if (wid == 0) {
            int r = lane >> 3, j = lane & 7;
            float m = s.pM[r][j];
            float mm = m;
            mm = fmaxf(mm, __shfl_xor_sync(0xffffffffu, mm, 1));
            mm = fmaxf(mm, __shfl_xor_sync(0xffffffffu, mm, 2));
            mm = fmaxf(mm, __shfl_xor_sync(0xffffffffu, mm, 4));
            float cf = __expf(m - mm);
            float zc = cf * s.pZ[r][j];
            float zs = zc;
            zs += __shfl_xor_sync(0xffffffffu, zs, 1);
            zs += __shfl_xor_sync(0xffffffffu, zs, 2);
            zs += __shfl_xor_sync(0xffffffffu, zs, 4);
            s.coef[r][j] = cf;
            if (j == 0) s.invZ[r] = 1.f / zs;
        }
        __syncthreads();

        // ---- parallel: r-vector combine | ww softmax -> wwprev | v -> vprev ----
        if (tid < BT * Vd / 4) {
            int r = tid >> 6, c4 = tid & 63;
            float4 acc = make_float4(0.f, 0.f, 0.f, 0.f);
            #pragma unroll
            for (int j = 0; j < 8; j++) {
                float cf = s.coef[r][j];
                float4 p = s.scratch[(r * 8 + j) * 64 + c4];
                acc.x = fmaf(cf, p.x, acc.x); acc.y = fmaf(cf, p.y, acc.y);
                acc.z = fmaf(cf, p.z, acc.z); acc.w = fmaf(cf, p.w, acc.w);
            }
            float iz = s.invZ[r];
            acc.x *= iz; acc.y *= iz; acc.z *= iz; acc.w *= iz;
            ((float*)(s.woT + Cd + c4 * 4 + 0))[r] = acc.x;
            ((float*)(s.woT + Cd + c4 * 4 + 1))[r] = acc.y;
            ((float*)(s.woT + Cd + c4 * 4 + 2))[r] = acc.z;
            ((float*)(s.woT + Cd + c4 * 4 + 3))[r] = acc.w;
            ((float*)(s.ciT + Ed + c4 * 4 + 0))[r] = acc.x;
            ((float*)(s.ciT + Ed + c4 * 4 + 1))[r] = acc.y;
            ((float*)(s.ciT + Ed + c4 * 4 + 2))[r] = acc.z;
            ((float*)(s.ciT + Ed + c4 * 4 + 3))[r] = acc.w;
        } else if (wid >= 16 && wid < 16 + BT) {
            int r = wid - 16;
            float* rowp = s.ww[r];
            float v0 = rowp[lane], v1 = rowp[lane + 32], v2 = rowp[lane + 64], v3 = rowp[lane + 96];
            float mx = wmax(fmaxf(fmaxf(v0, v1), fmaxf(v2, v3)));
            float e0 = __expf(v0 - mx), e1 = __expf(v1 - mx), e2 = __expf(v2 - mx), e3 = __expf(v3 - mx);
            float sm = wsum(e0 + e1 + e2 + e3);
            float inv = 1.f / sm;
            s.wwprev[r][lane]      = e0 * inv;
            s.wwprev[r][lane + 32] = e1 * inv;
            s.wwprev[r][lane + 64] = e2 * inv;
            s.wwprev[r][lane + 96] = e3 * inv;
        } else if (wid >= 24) {
            int i = tid - 24 * 32;              // 0..255
            int r = i >> 6, c4 = i & 63;
            ((float4*)s.vprev[r])[c4] = ((const float4*)(s.o[r] + Vd))[c4];
        }
        __syncthreads();

        // out = [co | r] @ Wo + bo -> global
        gemm_main<Cd + Vd, Od>(s.woT, Wo, bo, s.scratch);
        gemm_combine<Od, NTH / (Od / 4), false, 2>(s.scratch,
                                                   out + ((size_t)t * Bd + b0) * Od,
                                                   nullptr, (size_t)Od);
        __syncthreads();
    }
}

extern "C" void kernel_launch(void* const* d_in, const int* in_sizes, int n_in,
                              void* d_out, int out_size)
{
    (void)in_sizes; (void)n_in; (void)out_size;
    const float* x         = (const float*)d_in[0];
    const float* W1        = (const float*)d_in[1];
    const float* b1        = (const float*)d_in[2];
    const float* W2        = (const float*)d_in[3];
    const float* b2        = (const float*)d_in[4];
    const float* Wr        = (const float*)d_in[5];
    const float* br        = (const float*)d_in[6];
    const float* Ww        = (const float*)d_in[7];
    const float* bw        = (const float*)d_in[8];
    const float* Wo        = (const float*)d_in[9];
    const float* bo        = (const float*)d_in[10];
    const float* init_read = (const float*)d_in[11];
    const float* mem0      = (const float*)d_in[12];
    float* out = (float*)d_out;

    int smem = (int)sizeof(SM);
    cudaFuncSetAttribute(ntm_kernel, cudaFuncAttributeMaxDynamicSharedMemorySize, smem);
    ntm_kernel<<<NCTA, NTH, smem>>>(x, W1, b1, W2, b2, Wr, br, Ww, bw, Wo, bo,
                                    init_read, mem0, out);
}